// round 16
// baseline (speedup 1.0000x reference)
#include <cuda_runtime.h>
#include <cuda_fp16.h>
#include <cstdint>

#define TOKENS 200704          // 16*16*16*49
#define DIM 256
#define NQKV 768
#define NWIN 4096
#define WQ 49
#define NKEY 53
#define NMEM 4
#define DH 32
#define NHEADS 8

typedef unsigned long long ull;

// ---- scratch (static device globals; no runtime allocation) ----
// q: hi-only fp16 pair-words, PRE-SCALED, word-group PERMUTED (g -> 2(g&3)|(g>>2)).
__device__ uint32_t g_q[(size_t)TOKENS * 128];    // 103 MB
// k,v: hi-only fp16 pair-words, PERMUTED. k = words 0..127, v = 128..255.
__device__ uint32_t g_kv[(size_t)TOKENS * 256];   // 205 MB
// fragment-major A (fp16 hi only): frag(m16,k16) -> 32 lanes x uint4
__device__ uint4 g_fah[(size_t)(TOKENS / 16) * 16 * 32];
// fragment-major B hi-only, k16-PAIRED: (n8, k16pair) -> 32 lanes x uint4
__device__ uint4 g_fb1[(NQKV / 8) * 8 * 32];
__device__ uint4 g_fb2[(DIM / 8) * 8 * 32];
// pre-split memory kv (hi-only, PERMUTED): [h][key 0..3][word 0..15]
__device__ uint32_t g_mk[512], g_mv[512];

// ---- helpers ----
__device__ __forceinline__ uint32_t hpack(float x, float y) {
    __half2 t = __floats2half2_rn(x, y);   // low half = x
    return *(uint32_t*)&t;
}
__device__ __forceinline__ uint32_t prmt(uint32_t a, uint32_t b, uint32_t sel) {
    uint32_t d;
    asm("prmt.b32 %0, %1, %2, %3;" : "=r"(d) : "r"(a), "r"(b), "r"(sel));
    return d;
}
__device__ __forceinline__ int wperm(int g) {     // within-8 word permutation
    return ((g & 3) << 1) | (g >> 2);
}
__device__ __forceinline__ void mma4(float* d,
    uint32_t a0, uint32_t a1, uint32_t a2, uint32_t a3, uint32_t b0, uint32_t b1) {
    asm volatile("mma.sync.aligned.m16n8k16.row.col.f32.f16.f16.f32 "
        "{%0,%1,%2,%3}, {%4,%5,%6,%7}, {%8,%9}, {%0,%1,%2,%3};"
        : "+f"(d[0]), "+f"(d[1]), "+f"(d[2]), "+f"(d[3])
        : "r"(a0), "r"(a1), "r"(a2), "r"(a3), "r"(b0), "r"(b1));
}

// ============================================================
// Pre-split memory kv (hi-only, permuted). One block.
// ============================================================
__global__ void mem_split(const float* __restrict__ mem_kv) {
    int t = threadIdx.x;                 // 0..1023 = [kv][h][key][p]
    int p = t & 15, key = (t >> 4) & 3, h = (t >> 6) & 7, kv = t >> 9;
    float2 v = *(const float2*)(mem_kv + (size_t)(((kv * 8 + h) * 4 + key) * 32) + 2 * p);
    uint32_t hw = hpack(v.x, v.y);
    int pp = (p & 8) | wperm(p & 7);
    if (kv == 0) g_mk[(h * 4 + key) * 16 + pp] = hw;
    else         g_mv[(h * 4 + key) * 16 + pp] = hw;
}

// ============================================================
// Fused LayerNorm + A-fragment pack (fp16 hi only). CTA = 32 tokens.
// ============================================================
__global__ void __launch_bounds__(256) ln_pack_a(
    const float* __restrict__ X, const float* __restrict__ gamma)
{
    __shared__ float smu[32], srs[32];
    const int t0 = blockIdx.x * 32;
    const int w = threadIdx.x >> 5, lane = threadIdx.x & 31;

#pragma unroll
    for (int i = 0; i < 4; i++) {
        int tok = t0 + w * 4 + i;
        const float4* row = (const float4*)(X + (size_t)tok * DIM);
        float4 v0 = row[lane * 2], v1 = row[lane * 2 + 1];
        float s  = (v0.x + v0.y) + (v0.z + v0.w) + (v1.x + v1.y) + (v1.z + v1.w);
        float ss = v0.x * v0.x + v0.y * v0.y + v0.z * v0.z + v0.w * v0.w
                 + v1.x * v1.x + v1.y * v1.y + v1.z * v1.z + v1.w * v1.w;
#pragma unroll
        for (int o = 16; o; o >>= 1) {
            s  += __shfl_xor_sync(0xffffffffu, s, o);
            ss += __shfl_xor_sync(0xffffffffu, ss, o);
        }
        if (lane == 0) {
            float mu = s * (1.f / DIM);
            float var = fmaxf(ss * (1.f / DIM) - mu * mu, 0.f);
            smu[w * 4 + i] = mu;
            srs[w * 4 + i] = rsqrtf(var + 1e-5f);
        }
    }
    __syncthreads();

#pragma unroll
    for (int fi = 0; fi < 4; fi++) {
        const int f = w * 4 + fi;
        const int lm = f >> 4, k16 = f & 15;
        const int rl0 = lm * 16 + (lane >> 2);
        const int rl1 = rl0 + 8;
        const int row0 = t0 + rl0, row1 = t0 + rl1;
        const int kc = (k16 << 4) + ((lane & 3) << 1);

        float2 x00 = *(const float2*)(X + (size_t)row0 * DIM + kc);
        float2 x01 = *(const float2*)(X + (size_t)row0 * DIM + kc + 8);
        float2 x10 = *(const float2*)(X + (size_t)row1 * DIM + kc);
        float2 x11 = *(const float2*)(X + (size_t)row1 * DIM + kc + 8);
        float mu0 = smu[rl0], rs0 = srs[rl0];
        float mu1 = smu[rl1], rs1 = srs[rl1];
        float2 g0 = *(const float2*)(gamma + kc);
        float2 g1 = *(const float2*)(gamma + kc + 8);
        x00.x = (x00.x - mu0) * rs0 * g0.x; x00.y = (x00.y - mu0) * rs0 * g0.y;
        x01.x = (x01.x - mu0) * rs0 * g1.x; x01.y = (x01.y - mu0) * rs0 * g1.y;
        x10.x = (x10.x - mu1) * rs1 * g0.x; x10.y = (x10.y - mu1) * rs1 * g0.y;
        x11.x = (x11.x - mu1) * rs1 * g1.x; x11.y = (x11.y - mu1) * rs1 * g1.y;

        uint4 h;
        h.x = hpack(x00.x, x00.y);
        h.y = hpack(x10.x, x10.y);
        h.z = hpack(x01.x, x01.y);
        h.w = hpack(x11.x, x11.y);
        const size_t fragid = (size_t)(t0 / 16 + lm) * 16 + k16;
        g_fah[fragid * 32 + lane] = h;
    }
}

// ============================================================
// Pack B (weights, [K=256][N]) into hi-only, k16-paired B-frag layout.
// ============================================================
__global__ void __launch_bounds__(256) pack_b(
    const float* __restrict__ W, uint4* __restrict__ B, int N)
{
    const int t = blockIdx.x * 256 + threadIdx.x;
    const int lane = t & 31;
    const int k16 = (t >> 5) & 15;
    const int n8 = t >> 9;
    const int k = (k16 << 4) + ((lane & 3) << 1);
    const int n = (n8 << 3) + (lane >> 2);
    float w0 = W[(size_t)k * N + n];
    float w1 = W[(size_t)(k + 1) * N + n];
    float w2 = W[(size_t)(k + 8) * N + n];
    float w3 = W[(size_t)(k + 9) * N + n];
    uint2 h = make_uint2(hpack(w0, w1), hpack(w2, w3));
    uint2* dst = (uint2*)B;
    dst[(size_t)(((n8 * 8 + (k16 >> 1)) * 32 + lane) * 2 + (k16 & 1))] = h;
}

// ============================================================
// Warp-MMA GEMM: CTA 128x128, 4 warps of 64x64, K=256.
// fp16 single product (hi*hi). B loaded as k16-paired uint4.
// MODE 0: fp32 C store. MODE 1: permuted hi-only STG.64 to g_q / g_kv.
// ============================================================
template<int MODE>
__global__ void __launch_bounds__(128, 2) gemm_mma(
    const uint4* __restrict__ FAh,
    const uint4* __restrict__ FB,
    float* __restrict__ C, int N)
{
    const int lane = threadIdx.x & 31;
    const int wid = threadIdx.x >> 5;
    const int m16b = blockIdx.y * 8 + (wid & 1) * 4;
    const int n8b  = blockIdx.x * 16 + (wid >> 1) * 8;   // even

    const uint4* pAh = FAh + (size_t)m16b * 16 * 32 + lane;
    const uint4* pB  = FB  + (size_t)n8b * 8 * 32 + lane;

    float acc[4][8][4];
#pragma unroll
    for (int i = 0; i < 4; i++)
#pragma unroll
        for (int j = 0; j < 8; j++)
#pragma unroll
            for (int r = 0; r < 4; r++) acc[i][j][r] = 0.f;

#pragma unroll 2
    for (int kkp = 0; kkp < 8; kkp++) {
        uint4 bq[8];
#pragma unroll
        for (int j = 0; j < 8; j++)
            bq[j] = pB[(j * 8 + kkp) * 32];
#pragma unroll
        for (int half = 0; half < 2; half++) {
            const int kk = kkp * 2 + half;
#pragma unroll
            for (int i = 0; i < 4; i++) {
                uint4 ah = pAh[(i * 16 + kk) * 32];
#pragma unroll
                for (int j = 0; j < 8; j++) {
                    if (half == 0) mma4(acc[i][j], ah.x, ah.y, ah.z, ah.w, bq[j].x, bq[j].y);
                    else           mma4(acc[i][j], ah.x, ah.y, ah.z, ah.w, bq[j].z, bq[j].w);
                }
            }
        }
    }

    const int r0 = (m16b << 4) + (lane >> 2);
    const int c0 = (n8b << 3) + ((lane & 3) << 1);
    if (MODE == 0) {
#pragma unroll
        for (int i = 0; i < 4; i++) {
            const size_t rowa = (size_t)(r0 + i * 16) * N;
            const size_t rowb = rowa + 8 * N;
#pragma unroll
            for (int j = 0; j < 8; j++) {
                *(float2*)(C + rowa + c0 + j * 8) = make_float2(acc[i][j][0], acc[i][j][1]);
                *(float2*)(C + rowb + c0 + j * 8) = make_float2(acc[i][j][2], acc[i][j][3]);
            }
        }
    } else {
        const bool isq = (blockIdx.x < 2);
        const float s = isq ? 0.17677669529663687f : 1.0f;   // fold 1/sqrt(32) into q
#pragma unroll
        for (int i = 0; i < 4; i++) {
            const size_t rowa = (size_t)(r0 + i * 16);
            const size_t rowb = rowa + 8;
#pragma unroll
            for (int jp = 0; jp < 4; jp++) {
                // permuted adjacent pair: frag 2jp (old g=tx) and 2jp+1 (old g=tx+4)
                const int nw = (n8b + 2 * jp) * 4 + 2 * (lane & 3);
                uint2 va = make_uint2(hpack(acc[i][2 * jp][0] * s,     acc[i][2 * jp][1] * s),
                                      hpack(acc[i][2 * jp + 1][0] * s, acc[i][2 * jp + 1][1] * s));
                uint2 vb = make_uint2(hpack(acc[i][2 * jp][2] * s,     acc[i][2 * jp][3] * s),
                                      hpack(acc[i][2 * jp + 1][2] * s, acc[i][2 * jp + 1][3] * s));
                if (isq) {
                    *(uint2*)&g_q[rowa * 128 + nw] = va;
                    *(uint2*)&g_q[rowb * 128 + nw] = vb;
                } else {
                    *(uint2*)&g_kv[rowa * 256 + nw - 128] = va;
                    *(uint2*)&g_kv[rowb * 256 + nw - 128] = vb;
                }
            }
        }
    }
}

// ============================================================
// Attention: tensor-core, hi-only fp16; K & Q loaded DIRECTLY from gmem
// (permuted layout -> one LDG.64 per frag-half); V transposed via smem.
// ============================================================
__global__ void __launch_bounds__(128, 6) attn_kernel(
    const float* __restrict__ bias_table)
{
    __shared__ uint32_t Vt[4 * 32 * 8];
    __shared__ float bias_s[169];
    __shared__ int tab_s[56];

    const int cta = blockIdx.x;
    const int b = cta >> 3, h = cta & 7;
    const int tid = threadIdx.x, wid = tid >> 5, lane = tid & 31;
    const size_t tok0 = (size_t)b * WQ;

    // ---- stage Vt (prmt recombine; source words permuted) ----
#pragma unroll
    for (int it = 0; it < 4; it++) {
        const int g = tid + it * 128;            // [k16][m][w], m = dh pair
        const int w = g & 7, m = (g >> 3) & 15, k16 = g >> 7;
        const int p = k16 * 8 + (w >> 1) + ((w & 1) << 2);   // key pair (old idx)
        const int pm = (m & 8) | wperm(m & 7);               // permuted source word
        uint32_t a = 0u, bb = 0u;
        if (p < 2) {
            a  = g_mv[(h * 4 + 2 * p) * 16 + pm];
            bb = g_mv[(h * 4 + 2 * p + 1) * 16 + pm];
        } else {
            const int t0 = 2 * p - NMEM;
            if (t0 < WQ)     a  = g_kv[(tok0 + t0) * 256 + 128 + h * 16 + pm];
            if (t0 + 1 < WQ) bb = g_kv[(tok0 + t0 + 1) * 256 + 128 + h * 16 + pm];
        }
        const int de = (k16 * 32 + 2 * m) * 8 + w;
        Vt[de]     = prmt(a, bb, 0x5410);
        Vt[de + 8] = prmt(a, bb, 0x7632);
    }
    for (int f = tid; f < 169; f += 128) bias_s[f] = bias_table[f * NHEADS + h];
    if (tid < WQ) { int yj = tid / 7, xj = tid % 7; tab_s[tid + NMEM] = yj * 13 + xj; }
    __syncthreads();

    // ---- Q A-frags: direct LDG.64 (permuted adjacency) ----
    const int tx = lane & 3;
    const int qr = lane >> 2;
    const int qc = tx * 2;
    const int ra = wid * 16 + qr, rb = ra + 8;
    const int raC = min(ra, WQ - 1), rbC = min(rb, WQ - 1);
    uint32_t qh[2][4];
#pragma unroll
    for (int k16 = 0; k16 < 2; k16++) {
        const int wq = h * 16 + k16 * 8 + 2 * tx;
        uint2 qa = *(const uint2*)&g_q[(tok0 + raC) * 128 + wq];
        uint2 qb = *(const uint2*)&g_q[(tok0 + rbC) * 128 + wq];
        qh[k16][0] = qa.x; qh[k16][2] = qa.y;
        qh[k16][1] = qb.x; qh[k16][3] = qb.y;
    }

    // ---- S = Q K^T, K B-frags direct from gmem ----
    float S[7][4];
#pragma unroll
    for (int n8 = 0; n8 < 7; n8++)
#pragma unroll
        for (int r = 0; r < 4; r++) S[n8][r] = 0.f;

    const int kn = lane >> 2;
#pragma unroll
    for (int k16 = 0; k16 < 2; k16++) {
        uint2 kf[7];
#pragma unroll
        for (int n8 = 0; n8 < 7; n8++) {
            const int key = n8 * 8 + kn;
            uint2 v = make_uint2(0u, 0u);
            if (key < NMEM)
                v = *(const uint2*)&g_mk[(h * 4 + key) * 16 + k16 * 8 + 2 * tx];
            else if (key < NKEY)
                v = *(const uint2*)&g_kv[(tok0 + key - NMEM) * 256 + h * 16 + k16 * 8 + 2 * tx];
            kf[n8] = v;
        }
#pragma unroll
        for (int n8 = 0; n8 < 7; n8++)
            mma4(S[n8], qh[k16][0], qh[k16][1], qh[k16][2], qh[k16][3], kf[n8].x, kf[n8].y);
    }

    // ---- bias + mask (scale folded into q) ----
    const int base_ra = (raC / 7 + 6) * 13 + raC % 7 + 6;
    const int base_rb = (rbC / 7 + 6) * 13 + rbC % 7 + 6;
#pragma unroll
    for (int n8 = 0; n8 < 7; n8++) {
#pragma unroll
        for (int e = 0; e < 2; e++) {
            const int col = n8 * 8 + qc + e;
            if (col >= NKEY) {
                S[n8][e] = -1e30f; S[n8][2 + e] = -1e30f;
            } else if (col >= NMEM) {
                const int t = tab_s[col];
                S[n8][e]     += bias_s[base_ra - t];
                S[n8][2 + e] += bias_s[base_rb - t];
            }
        }
    }

    // ---- softmax (rows ra, rb), fp32 exact ----
    float mA = -1e30f, mB = -1e30f;
#pragma unroll
    for (int n8 = 0; n8 < 7; n8++) {
        mA = fmaxf(mA, fmaxf(S[n8][0], S[n8][1]));
        mB = fmaxf(mB, fmaxf(S[n8][2], S[n8][3]));
    }
    mA = fmaxf(mA, __shfl_xor_sync(0xffffffffu, mA, 1));
    mA = fmaxf(mA, __shfl_xor_sync(0xffffffffu, mA, 2));
    mB = fmaxf(mB, __shfl_xor_sync(0xffffffffu, mB, 1));
    mB = fmaxf(mB, __shfl_xor_sync(0xffffffffu, mB, 2));
    float lA = 0.f, lB = 0.f;
#pragma unroll
    for (int n8 = 0; n8 < 7; n8++) {
        S[n8][0] = __expf(S[n8][0] - mA); lA += S[n8][0];
        S[n8][1] = __expf(S[n8][1] - mA); lA += S[n8][1];
        S[n8][2] = __expf(S[n8][2] - mB); lB += S[n8][2];
        S[n8][3] = __expf(S[n8][3] - mB); lB += S[n8][3];
    }
    lA += __shfl_xor_sync(0xffffffffu, lA, 1);
    lA += __shfl_xor_sync(0xffffffffu, lA, 2);
    lB += __shfl_xor_sync(0xffffffffu, lB, 1);
    lB += __shfl_xor_sync(0xffffffffu, lB, 2);
    const float invA = 1.f / lA, invB = 1.f / lB;
#pragma unroll
    for (int n8 = 0; n8 < 7; n8++) {
        S[n8][0] *= invA; S[n8][1] *= invA;
        S[n8][2] *= invB; S[n8][3] *= invB;
    }

    // ---- pack P into A-frags (hi only) ----
    uint32_t ph[4][4];
#pragma unroll
    for (int k16 = 0; k16 < 4; k16++) {
        const int na = 2 * k16, nb = na + 1;
        ph[k16][0] = hpack(S[na][0], S[na][1]);
        ph[k16][1] = hpack(S[na][2], S[na][3]);
        if (nb < 7) {
            ph[k16][2] = hpack(S[nb][0], S[nb][1]);
            ph[k16][3] = hpack(S[nb][2], S[nb][3]);
        } else {
            ph[k16][2] = 0; ph[k16][3] = 0;
        }
    }

    // ---- O = P V (single product) ----
    const int q2w = tx * 2;
    float O[4][4];
#pragma unroll
    for (int nv = 0; nv < 4; nv++)
#pragma unroll
        for (int r = 0; r < 4; r++) O[nv][r] = 0.f;
#pragma unroll
    for (int k16 = 0; k16 < 4; k16++) {
#pragma unroll
        for (int nv = 0; nv < 4; nv++) {
            const int a = (k16 * 32 + nv * 8 + kn) * 8 + q2w;
            const uint2 vh = *(const uint2*)&Vt[a];
            mma4(O[nv], ph[k16][0], ph[k16][1], ph[k16][2], ph[k16][3], vh.x, vh.y);
        }
    }

    // ---- epilogue: direct A-frag word stores for out GEMM (hi only) ----
#pragma unroll
    for (int half = 0; half < 2; half++) {
        const int row = half ? rb : ra;
        if (row < WQ) {
            const size_t tok = tok0 + row;
            const size_t m16g = tok >> 4;
            const int rr = (int)(tok & 15);
            const int comp_base = (rr < 8) ? 0 : 1;
            const int lane_t = 4 * (rr & 7) + tx;
#pragma unroll
            for (int nv = 0; nv < 4; nv++) {
                const int col = nv * 8 + qc;
                const int c16 = nv >> 1;
                const size_t fragid = m16g * 16 + 2 * h + c16;
                const int comp = comp_base + ((col & 8) ? 2 : 0);
                ((uint32_t*)(g_fah + fragid * 32 + lane_t))[comp] =
                    hpack(O[nv][half * 2], O[nv][half * 2 + 1]);
            }
        }
    }
}

// ============================================================
extern "C" void kernel_launch(void* const* d_in, const int* in_sizes, int n_in,
                              void* d_out, int out_size) {
    const float* x          = (const float*)d_in[0];
    const float* gamma      = (const float*)d_in[1];
    const float* w_qkv      = (const float*)d_in[2];
    const float* mem_kv     = (const float*)d_in[3];
    const float* bias_table = (const float*)d_in[4];
    const float* w_out      = (const float*)d_in[5];
    float* out = (float*)d_out;

    uint4 *fah, *fb1, *fb2;
    cudaGetSymbolAddress((void**)&fah, g_fah);
    cudaGetSymbolAddress((void**)&fb1, g_fb1);
    cudaGetSymbolAddress((void**)&fb2, g_fb2);

    mem_split<<<1, 1024>>>(mem_kv);
    pack_b<<<(NQKV / 8) * 16 * 32 / 256, 256>>>(w_qkv, fb1, NQKV);
    pack_b<<<(DIM / 8) * 16 * 32 / 256, 256>>>(w_out, fb2, DIM);
    ln_pack_a<<<TOKENS / 32, 256>>>(x, gamma);
    gemm_mma<1><<<dim3(NQKV / 128, TOKENS / 128), 128>>>(fah, fb1, nullptr, NQKV);
    attn_kernel<<<NWIN * NHEADS, 128>>>(bias_table);
    gemm_mma<0><<<dim3(DIM / 128, TOKENS / 128), 128>>>(fah, fb2, out, DIM);
}

// round 17
// speedup vs baseline: 1.0003x; 1.0003x over previous
#include <cuda_runtime.h>
#include <cuda_fp16.h>
#include <cstdint>

#define TOKENS 200704          // 16*16*16*49
#define DIM 256
#define NQKV 768
#define NWIN 4096
#define WQ 49
#define NKEY 53
#define NMEM 4
#define DH 32
#define NHEADS 8

typedef unsigned long long ull;

// ---- scratch (static device globals; no runtime allocation) ----
// q: hi-only fp16 pair-words, PRE-SCALED, word-group PERMUTED (g -> 2(g&3)|(g>>2)).
__device__ uint32_t g_q[(size_t)TOKENS * 128];    // 103 MB
// k,v: hi-only fp16 pair-words, PERMUTED. k = words 0..127, v = 128..255.
__device__ uint32_t g_kv[(size_t)TOKENS * 256];   // 205 MB
// fragment-major A (fp16 hi only): frag(m16,k16) -> 32 lanes x uint4
__device__ uint4 g_fah[(size_t)(TOKENS / 16) * 16 * 32];
// fragment-major B hi-only, k16-PAIRED: (n8, k16pair) -> 32 lanes x uint4
__device__ uint4 g_fb1[(NQKV / 8) * 8 * 32];
__device__ uint4 g_fb2[(DIM / 8) * 8 * 32];
// pre-split memory kv (hi-only, PERMUTED): [h][key 0..3][word 0..15]
__device__ uint32_t g_mk[512], g_mv[512];

// ---- helpers ----
__device__ __forceinline__ uint32_t hpack(float x, float y) {
    __half2 t = __floats2half2_rn(x, y);   // low half = x
    return *(uint32_t*)&t;
}
__device__ __forceinline__ uint32_t prmt(uint32_t a, uint32_t b, uint32_t sel) {
    uint32_t d;
    asm("prmt.b32 %0, %1, %2, %3;" : "=r"(d) : "r"(a), "r"(b), "r"(sel));
    return d;
}
__device__ __forceinline__ int wperm(int g) {     // within-8 word permutation
    return ((g & 3) << 1) | (g >> 2);
}
__device__ __forceinline__ void mma4(float* d,
    uint32_t a0, uint32_t a1, uint32_t a2, uint32_t a3, uint32_t b0, uint32_t b1) {
    asm volatile("mma.sync.aligned.m16n8k16.row.col.f32.f16.f16.f32 "
        "{%0,%1,%2,%3}, {%4,%5,%6,%7}, {%8,%9}, {%0,%1,%2,%3};"
        : "+f"(d[0]), "+f"(d[1]), "+f"(d[2]), "+f"(d[3])
        : "r"(a0), "r"(a1), "r"(a2), "r"(a3), "r"(b0), "r"(b1));
}

// ============================================================
// Pre-split memory kv (hi-only, permuted). One block.
// ============================================================
__global__ void mem_split(const float* __restrict__ mem_kv) {
    int t = threadIdx.x;                 // 0..1023 = [kv][h][key][p]
    int p = t & 15, key = (t >> 4) & 3, h = (t >> 6) & 7, kv = t >> 9;
    float2 v = *(const float2*)(mem_kv + (size_t)(((kv * 8 + h) * 4 + key) * 32) + 2 * p);
    uint32_t hw = hpack(v.x, v.y);
    int pp = (p & 8) | wperm(p & 7);
    if (kv == 0) g_mk[(h * 4 + key) * 16 + pp] = hw;
    else         g_mv[(h * 4 + key) * 16 + pp] = hw;
}

// ============================================================
// Fused LayerNorm + A-fragment pack (fp16 hi only). CTA = 32 tokens.
// ============================================================
__global__ void __launch_bounds__(256) ln_pack_a(
    const float* __restrict__ X, const float* __restrict__ gamma)
{
    __shared__ float smu[32], srs[32];
    const int t0 = blockIdx.x * 32;
    const int w = threadIdx.x >> 5, lane = threadIdx.x & 31;

#pragma unroll
    for (int i = 0; i < 4; i++) {
        int tok = t0 + w * 4 + i;
        const float4* row = (const float4*)(X + (size_t)tok * DIM);
        float4 v0 = row[lane * 2], v1 = row[lane * 2 + 1];
        float s  = (v0.x + v0.y) + (v0.z + v0.w) + (v1.x + v1.y) + (v1.z + v1.w);
        float ss = v0.x * v0.x + v0.y * v0.y + v0.z * v0.z + v0.w * v0.w
                 + v1.x * v1.x + v1.y * v1.y + v1.z * v1.z + v1.w * v1.w;
#pragma unroll
        for (int o = 16; o; o >>= 1) {
            s  += __shfl_xor_sync(0xffffffffu, s, o);
            ss += __shfl_xor_sync(0xffffffffu, ss, o);
        }
        if (lane == 0) {
            float mu = s * (1.f / DIM);
            float var = fmaxf(ss * (1.f / DIM) - mu * mu, 0.f);
            smu[w * 4 + i] = mu;
            srs[w * 4 + i] = rsqrtf(var + 1e-5f);
        }
    }
    __syncthreads();

#pragma unroll
    for (int fi = 0; fi < 4; fi++) {
        const int f = w * 4 + fi;
        const int lm = f >> 4, k16 = f & 15;
        const int rl0 = lm * 16 + (lane >> 2);
        const int rl1 = rl0 + 8;
        const int row0 = t0 + rl0, row1 = t0 + rl1;
        const int kc = (k16 << 4) + ((lane & 3) << 1);

        float2 x00 = *(const float2*)(X + (size_t)row0 * DIM + kc);
        float2 x01 = *(const float2*)(X + (size_t)row0 * DIM + kc + 8);
        float2 x10 = *(const float2*)(X + (size_t)row1 * DIM + kc);
        float2 x11 = *(const float2*)(X + (size_t)row1 * DIM + kc + 8);
        float mu0 = smu[rl0], rs0 = srs[rl0];
        float mu1 = smu[rl1], rs1 = srs[rl1];
        float2 g0 = *(const float2*)(gamma + kc);
        float2 g1 = *(const float2*)(gamma + kc + 8);
        x00.x = (x00.x - mu0) * rs0 * g0.x; x00.y = (x00.y - mu0) * rs0 * g0.y;
        x01.x = (x01.x - mu0) * rs0 * g1.x; x01.y = (x01.y - mu0) * rs0 * g1.y;
        x10.x = (x10.x - mu1) * rs1 * g0.x; x10.y = (x10.y - mu1) * rs1 * g0.y;
        x11.x = (x11.x - mu1) * rs1 * g1.x; x11.y = (x11.y - mu1) * rs1 * g1.y;

        uint4 h;
        h.x = hpack(x00.x, x00.y);
        h.y = hpack(x10.x, x10.y);
        h.z = hpack(x01.x, x01.y);
        h.w = hpack(x11.x, x11.y);
        const size_t fragid = (size_t)(t0 / 16 + lm) * 16 + k16;
        g_fah[fragid * 32 + lane] = h;
    }
}

// ============================================================
// Pack B (weights, [K=256][N]) into hi-only, k16-paired B-frag layout.
// ============================================================
__global__ void __launch_bounds__(256) pack_b(
    const float* __restrict__ W, uint4* __restrict__ B, int N)
{
    const int t = blockIdx.x * 256 + threadIdx.x;
    const int lane = t & 31;
    const int k16 = (t >> 5) & 15;
    const int n8 = t >> 9;
    const int k = (k16 << 4) + ((lane & 3) << 1);
    const int n = (n8 << 3) + (lane >> 2);
    float w0 = W[(size_t)k * N + n];
    float w1 = W[(size_t)(k + 1) * N + n];
    float w2 = W[(size_t)(k + 8) * N + n];
    float w3 = W[(size_t)(k + 9) * N + n];
    uint2 h = make_uint2(hpack(w0, w1), hpack(w2, w3));
    uint2* dst = (uint2*)B;
    dst[(size_t)(((n8 * 8 + (k16 >> 1)) * 32 + lane) * 2 + (k16 & 1))] = h;
}

// ============================================================
// Warp-MMA GEMM: CTA 128x128, 4 warps of 64x64, K=256.
// fp16 single product (hi*hi). B loaded as k16-paired uint4.
// MODE 0: fp32 C store. MODE 1: permuted hi-only STG.64 to g_q / g_kv.
// ============================================================
template<int MODE>
__global__ void __launch_bounds__(128, 2) gemm_mma(
    const uint4* __restrict__ FAh,
    const uint4* __restrict__ FB,
    float* __restrict__ C, int N)
{
    const int lane = threadIdx.x & 31;
    const int wid = threadIdx.x >> 5;
    const int m16b = blockIdx.y * 8 + (wid & 1) * 4;
    const int n8b  = blockIdx.x * 16 + (wid >> 1) * 8;   // even

    const uint4* pAh = FAh + (size_t)m16b * 16 * 32 + lane;
    const uint4* pB  = FB  + (size_t)n8b * 8 * 32 + lane;

    float acc[4][8][4];
#pragma unroll
    for (int i = 0; i < 4; i++)
#pragma unroll
        for (int j = 0; j < 8; j++)
#pragma unroll
            for (int r = 0; r < 4; r++) acc[i][j][r] = 0.f;

#pragma unroll 2
    for (int kkp = 0; kkp < 8; kkp++) {
        uint4 bq[8];
#pragma unroll
        for (int j = 0; j < 8; j++)
            bq[j] = pB[(j * 8 + kkp) * 32];
#pragma unroll
        for (int half = 0; half < 2; half++) {
            const int kk = kkp * 2 + half;
#pragma unroll
            for (int i = 0; i < 4; i++) {
                uint4 ah = pAh[(i * 16 + kk) * 32];
#pragma unroll
                for (int j = 0; j < 8; j++) {
                    if (half == 0) mma4(acc[i][j], ah.x, ah.y, ah.z, ah.w, bq[j].x, bq[j].y);
                    else           mma4(acc[i][j], ah.x, ah.y, ah.z, ah.w, bq[j].z, bq[j].w);
                }
            }
        }
    }

    const int r0 = (m16b << 4) + (lane >> 2);
    const int c0 = (n8b << 3) + ((lane & 3) << 1);
    if (MODE == 0) {
#pragma unroll
        for (int i = 0; i < 4; i++) {
            const size_t rowa = (size_t)(r0 + i * 16) * N;
            const size_t rowb = rowa + 8 * N;
#pragma unroll
            for (int j = 0; j < 8; j++) {
                *(float2*)(C + rowa + c0 + j * 8) = make_float2(acc[i][j][0], acc[i][j][1]);
                *(float2*)(C + rowb + c0 + j * 8) = make_float2(acc[i][j][2], acc[i][j][3]);
            }
        }
    } else {
        const bool isq = (blockIdx.x < 2);
        const float s = isq ? 0.17677669529663687f : 1.0f;   // fold 1/sqrt(32) into q
#pragma unroll
        for (int i = 0; i < 4; i++) {
            const size_t rowa = (size_t)(r0 + i * 16);
            const size_t rowb = rowa + 8;
#pragma unroll
            for (int jp = 0; jp < 4; jp++) {
                // permuted adjacent pair: frag 2jp (old g=tx) and 2jp+1 (old g=tx+4)
                const int nw = (n8b + 2 * jp) * 4 + 2 * (lane & 3);
                uint2 va = make_uint2(hpack(acc[i][2 * jp][0] * s,     acc[i][2 * jp][1] * s),
                                      hpack(acc[i][2 * jp + 1][0] * s, acc[i][2 * jp + 1][1] * s));
                uint2 vb = make_uint2(hpack(acc[i][2 * jp][2] * s,     acc[i][2 * jp][3] * s),
                                      hpack(acc[i][2 * jp + 1][2] * s, acc[i][2 * jp + 1][3] * s));
                if (isq) {
                    *(uint2*)&g_q[rowa * 128 + nw] = va;
                    *(uint2*)&g_q[rowb * 128 + nw] = vb;
                } else {
                    *(uint2*)&g_kv[rowa * 256 + nw - 128] = va;
                    *(uint2*)&g_kv[rowb * 256 + nw - 128] = vb;
                }
            }
        }
    }
}

// ============================================================
// Attention: tensor-core, hi-only fp16; K & Q loaded DIRECTLY from gmem
// (permuted layout -> one LDG.64 per frag-half); V transposed via smem.
// ============================================================
__global__ void __launch_bounds__(128, 6) attn_kernel(
    const float* __restrict__ bias_table)
{
    __shared__ uint32_t Vt[4 * 32 * 8];
    __shared__ float bias_s[169];
    __shared__ int tab_s[56];

    const int cta = blockIdx.x;
    const int b = cta >> 3, h = cta & 7;
    const int tid = threadIdx.x, wid = tid >> 5, lane = tid & 31;
    const size_t tok0 = (size_t)b * WQ;

    // ---- stage Vt (prmt recombine; source words permuted) ----
#pragma unroll
    for (int it = 0; it < 4; it++) {
        const int g = tid + it * 128;            // [k16][m][w], m = dh pair
        const int w = g & 7, m = (g >> 3) & 15, k16 = g >> 7;
        const int p = k16 * 8 + (w >> 1) + ((w & 1) << 2);   // key pair (old idx)
        const int pm = (m & 8) | wperm(m & 7);               // permuted source word
        uint32_t a = 0u, bb = 0u;
        if (p < 2) {
            a  = g_mv[(h * 4 + 2 * p) * 16 + pm];
            bb = g_mv[(h * 4 + 2 * p + 1) * 16 + pm];
        } else {
            const int t0 = 2 * p - NMEM;
            if (t0 < WQ)     a  = g_kv[(tok0 + t0) * 256 + 128 + h * 16 + pm];
            if (t0 + 1 < WQ) bb = g_kv[(tok0 + t0 + 1) * 256 + 128 + h * 16 + pm];
        }
        const int de = (k16 * 32 + 2 * m) * 8 + w;
        Vt[de]     = prmt(a, bb, 0x5410);
        Vt[de + 8] = prmt(a, bb, 0x7632);
    }
    for (int f = tid; f < 169; f += 128) bias_s[f] = bias_table[f * NHEADS + h];
    if (tid < WQ) { int yj = tid / 7, xj = tid % 7; tab_s[tid + NMEM] = yj * 13 + xj; }
    __syncthreads();

    // ---- Q A-frags: direct LDG.64 (permuted adjacency) ----
    const int tx = lane & 3;
    const int qr = lane >> 2;
    const int qc = tx * 2;
    const int ra = wid * 16 + qr, rb = ra + 8;
    const int raC = min(ra, WQ - 1), rbC = min(rb, WQ - 1);
    uint32_t qh[2][4];
#pragma unroll
    for (int k16 = 0; k16 < 2; k16++) {
        const int wq = h * 16 + k16 * 8 + 2 * tx;
        uint2 qa = *(const uint2*)&g_q[(tok0 + raC) * 128 + wq];
        uint2 qb = *(const uint2*)&g_q[(tok0 + rbC) * 128 + wq];
        qh[k16][0] = qa.x; qh[k16][2] = qa.y;
        qh[k16][1] = qb.x; qh[k16][3] = qb.y;
    }

    // ---- S = Q K^T, K B-frags direct from gmem ----
    float S[7][4];
#pragma unroll
    for (int n8 = 0; n8 < 7; n8++)
#pragma unroll
        for (int r = 0; r < 4; r++) S[n8][r] = 0.f;

    const int kn = lane >> 2;
#pragma unroll
    for (int k16 = 0; k16 < 2; k16++) {
        uint2 kf[7];
#pragma unroll
        for (int n8 = 0; n8 < 7; n8++) {
            const int key = n8 * 8 + kn;
            uint2 v = make_uint2(0u, 0u);
            if (key < NMEM)
                v = *(const uint2*)&g_mk[(h * 4 + key) * 16 + k16 * 8 + 2 * tx];
            else if (key < NKEY)
                v = *(const uint2*)&g_kv[(tok0 + key - NMEM) * 256 + h * 16 + k16 * 8 + 2 * tx];
            kf[n8] = v;
        }
#pragma unroll
        for (int n8 = 0; n8 < 7; n8++)
            mma4(S[n8], qh[k16][0], qh[k16][1], qh[k16][2], qh[k16][3], kf[n8].x, kf[n8].y);
    }

    // ---- bias + mask (scale folded into q) ----
    const int base_ra = (raC / 7 + 6) * 13 + raC % 7 + 6;
    const int base_rb = (rbC / 7 + 6) * 13 + rbC % 7 + 6;
#pragma unroll
    for (int n8 = 0; n8 < 7; n8++) {
#pragma unroll
        for (int e = 0; e < 2; e++) {
            const int col = n8 * 8 + qc + e;
            if (col >= NKEY) {
                S[n8][e] = -1e30f; S[n8][2 + e] = -1e30f;
            } else if (col >= NMEM) {
                const int t = tab_s[col];
                S[n8][e]     += bias_s[base_ra - t];
                S[n8][2 + e] += bias_s[base_rb - t];
            }
        }
    }

    // ---- softmax (rows ra, rb), fp32 exact ----
    float mA = -1e30f, mB = -1e30f;
#pragma unroll
    for (int n8 = 0; n8 < 7; n8++) {
        mA = fmaxf(mA, fmaxf(S[n8][0], S[n8][1]));
        mB = fmaxf(mB, fmaxf(S[n8][2], S[n8][3]));
    }
    mA = fmaxf(mA, __shfl_xor_sync(0xffffffffu, mA, 1));
    mA = fmaxf(mA, __shfl_xor_sync(0xffffffffu, mA, 2));
    mB = fmaxf(mB, __shfl_xor_sync(0xffffffffu, mB, 1));
    mB = fmaxf(mB, __shfl_xor_sync(0xffffffffu, mB, 2));
    float lA = 0.f, lB = 0.f;
#pragma unroll
    for (int n8 = 0; n8 < 7; n8++) {
        S[n8][0] = __expf(S[n8][0] - mA); lA += S[n8][0];
        S[n8][1] = __expf(S[n8][1] - mA); lA += S[n8][1];
        S[n8][2] = __expf(S[n8][2] - mB); lB += S[n8][2];
        S[n8][3] = __expf(S[n8][3] - mB); lB += S[n8][3];
    }
    lA += __shfl_xor_sync(0xffffffffu, lA, 1);
    lA += __shfl_xor_sync(0xffffffffu, lA, 2);
    lB += __shfl_xor_sync(0xffffffffu, lB, 1);
    lB += __shfl_xor_sync(0xffffffffu, lB, 2);
    const float invA = 1.f / lA, invB = 1.f / lB;
#pragma unroll
    for (int n8 = 0; n8 < 7; n8++) {
        S[n8][0] *= invA; S[n8][1] *= invA;
        S[n8][2] *= invB; S[n8][3] *= invB;
    }

    // ---- pack P into A-frags (hi only) ----
    uint32_t ph[4][4];
#pragma unroll
    for (int k16 = 0; k16 < 4; k16++) {
        const int na = 2 * k16, nb = na + 1;
        ph[k16][0] = hpack(S[na][0], S[na][1]);
        ph[k16][1] = hpack(S[na][2], S[na][3]);
        if (nb < 7) {
            ph[k16][2] = hpack(S[nb][0], S[nb][1]);
            ph[k16][3] = hpack(S[nb][2], S[nb][3]);
        } else {
            ph[k16][2] = 0; ph[k16][3] = 0;
        }
    }

    // ---- O = P V (single product) ----
    const int q2w = tx * 2;
    float O[4][4];
#pragma unroll
    for (int nv = 0; nv < 4; nv++)
#pragma unroll
        for (int r = 0; r < 4; r++) O[nv][r] = 0.f;
#pragma unroll
    for (int k16 = 0; k16 < 4; k16++) {
#pragma unroll
        for (int nv = 0; nv < 4; nv++) {
            const int a = (k16 * 32 + nv * 8 + kn) * 8 + q2w;
            const uint2 vh = *(const uint2*)&Vt[a];
            mma4(O[nv], ph[k16][0], ph[k16][1], ph[k16][2], ph[k16][3], vh.x, vh.y);
        }
    }

    // ---- epilogue: direct A-frag word stores for out GEMM (hi only) ----
#pragma unroll
    for (int half = 0; half < 2; half++) {
        const int row = half ? rb : ra;
        if (row < WQ) {
            const size_t tok = tok0 + row;
            const size_t m16g = tok >> 4;
            const int rr = (int)(tok & 15);
            const int comp_base = (rr < 8) ? 0 : 1;
            const int lane_t = 4 * (rr & 7) + tx;
#pragma unroll
            for (int nv = 0; nv < 4; nv++) {
                const int col = nv * 8 + qc;
                const int c16 = nv >> 1;
                const size_t fragid = m16g * 16 + 2 * h + c16;
                const int comp = comp_base + ((col & 8) ? 2 : 0);
                ((uint32_t*)(g_fah + fragid * 32 + lane_t))[comp] =
                    hpack(O[nv][half * 2], O[nv][half * 2 + 1]);
            }
        }
    }
}

// ============================================================
extern "C" void kernel_launch(void* const* d_in, const int* in_sizes, int n_in,
                              void* d_out, int out_size) {
    const float* x          = (const float*)d_in[0];
    const float* gamma      = (const float*)d_in[1];
    const float* w_qkv      = (const float*)d_in[2];
    const float* mem_kv     = (const float*)d_in[3];
    const float* bias_table = (const float*)d_in[4];
    const float* w_out      = (const float*)d_in[5];
    float* out = (float*)d_out;

    uint4 *fah, *fb1, *fb2;
    cudaGetSymbolAddress((void**)&fah, g_fah);
    cudaGetSymbolAddress((void**)&fb1, g_fb1);
    cudaGetSymbolAddress((void**)&fb2, g_fb2);

    mem_split<<<1, 1024>>>(mem_kv);
    pack_b<<<(NQKV / 8) * 16 * 32 / 256, 256>>>(w_qkv, fb1, NQKV);
    pack_b<<<(DIM / 8) * 16 * 32 / 256, 256>>>(w_out, fb2, DIM);
    ln_pack_a<<<TOKENS / 32, 256>>>(x, gamma);
    gemm_mma<1><<<dim3(NQKV / 128, TOKENS / 128), 128>>>(fah, fb1, nullptr, NQKV);
    attn_kernel<<<NWIN * NHEADS, 128>>>(bias_table);
    gemm_mma<0><<<dim3(DIM / 128, TOKENS / 128), 128>>>(fah, fb2, out, DIM);
}